// round 15
// baseline (speedup 1.0000x reference)
#include <cuda_runtime.h>
#include <math.h>

#define BC 2048   // 32 batch * 64 channels
typedef unsigned long long u64;

// ---------------- scratch (device globals: allocation-free) ----------------
__device__ float2 d_X   [BC*128*65];
__device__ float2 d_T1  [BC*128*65];
__device__ float  d_u   [BC*128*128];
__device__ float2 d_P   [BC*64*128];
__device__ float2 d_U   [BC*64*33];
__device__ float2 d_T2  [BC*128*33];
__device__ float  d_w   [BC*64*64];
__device__ float2 d_G   [BC*64*33];
__device__ float2 d_xo  [BC*64*33];
// DFT matrices W_n[a*n+b] = e^{+2pi i (a*b mod n)/n} for n = 8..128, and flip (-wy, wx)
__device__ float2 d_W   [707124];
__device__ float2 d_Wf  [707124];

__host__ __device__ __forceinline__ long long offW(int n){
    long long x = n - 1;
    return x*(x+1)*(2*x+1)/6 - 140;   // sum_{m=8}^{n-1} m^2
}

// ---------------- packed f32x2 helpers ----------------
__device__ __forceinline__ u64 pk2(float lo, float hi){ u64 r; asm("mov.b64 %0, {%1,%2};" : "=l"(r) : "f"(lo), "f"(hi)); return r; }
__device__ __forceinline__ u64 sp2(float v){ u64 r; asm("mov.b64 %0, {%1,%1};" : "=l"(r) : "f"(v)); return r; }
__device__ __forceinline__ void upk(u64 p, float& lo, float& hi){ asm("mov.b64 {%0,%1}, %2;" : "=f"(lo), "=f"(hi) : "l"(p)); }
__device__ __forceinline__ u64 f2fma(u64 a, u64 b, u64 c){ u64 d; asm("fma.rn.f32x2 %0, %1, %2, %3;" : "=l"(d) : "l"(a), "l"(b), "l"(c)); return d; }

// ---------------- build all DFT matrices ----------------
__global__ void kW_kernel(){
    int n = blockIdx.x + 8;
    float2* W  = d_W  + offW(n);
    float2* Wf = d_Wf + offW(n);
    int nn = n*n;
    float inv = 1.0f/(float)n;
    for (int idx = threadIdx.x; idx < nn; idx += blockDim.x){
        int a = idx / n, b = idx - a*n;
        int t = (int)(((long long)a*(long long)b) % (long long)n);
        float s, c;
        sincospif(2.0f*(float)t*inv, &s, &c);
        W[idx]  = make_float2(c, s);
        Wf[idx] = make_float2(-s, c);
    }
}

// ---------------- K0a: row-axis forward DFT of input (4 rows/block, f32x2) ----------------
__global__ void k0a_kernel(const float* __restrict__ x){
    __shared__ float s0[2][4][128];
    int ty = threadIdx.y, tx = threadIdx.x;
    int img = blockIdx.y*blockDim.y + ty;
    int i0 = blockIdx.x*4;
    const float* xi = x + (size_t)img*128*128 + (size_t)i0*128;
    for (int idx = tx; idx < 4*128; idx += blockDim.x)
        s0[ty][idx>>7][idx&127] = xi[idx];
    __syncthreads();
    int k2 = tx;
    if (k2 >= 65) return;
    const u64* W = reinterpret_cast<const u64*>(d_W + offW(128));
    u64 P0=0,P1=0,P2=0,P3=0;
    for (int n2 = 0; n2 < 128; n2++){
        u64 w2 = W[n2*128 + k2];
        u64 v0=sp2(s0[ty][0][n2]), v1=sp2(s0[ty][1][n2]), v2=sp2(s0[ty][2][n2]), v3=sp2(s0[ty][3][n2]);
        P0 = f2fma(v0, w2, P0);
        P1 = f2fma(v1, w2, P1);
        P2 = f2fma(v2, w2, P2);
        P3 = f2fma(v3, w2, P3);
    }
    float2* T = d_T1 + (size_t)img*128*65;
    float ax, ay;
    upk(P0, ax, ay); T[(size_t)(i0+0)*65+k2] = make_float2(ax, -ay);
    upk(P1, ax, ay); T[(size_t)(i0+1)*65+k2] = make_float2(ax, -ay);
    upk(P2, ax, ay); T[(size_t)(i0+2)*65+k2] = make_float2(ax, -ay);
    upk(P3, ax, ay); T[(size_t)(i0+3)*65+k2] = make_float2(ax, -ay);
}

// ---------------- K0b: col-axis forward DFT -> X (with 1/128^2, f32x2) ----------------
__global__ void k0b_kernel(){
    __shared__ u64 sWc[4*128];   // conj(w) = (wx, -wy)
    __shared__ u64 sWs[4*128];   // swap(w) = (wy, wx)
    int ty = threadIdx.y, tx = threadIdx.x;
    int tid = ty*blockDim.x + tx, nt = blockDim.x*blockDim.y;
    int k1b = blockIdx.x*4;
    const float2* W = d_W + offW(128);
    for (int idx = tid; idx < 4*128; idx += nt){
        float2 w = W[(k1b + (idx>>7))*128 + (idx&127)];
        sWc[idx] = pk2(w.x, -w.y);
        sWs[idx] = pk2(w.y,  w.x);
    }
    __syncthreads();
    int img = blockIdx.y*blockDim.y + ty;
    int k2 = tx;
    if (k2 >= 65) return;
    const float2* Ai = d_T1 + (size_t)img*128*65;
    u64 acc[4] = {0,0,0,0};
    for (int i = 0; i < 128; i++){
        float2 v = Ai[(size_t)i*65 + k2];
        u64 svx = sp2(v.x), svy = sp2(v.y);
        #pragma unroll
        for (int a = 0; a < 4; a++)
            acc[a] = f2fma(svx, sWc[a*128 + i], f2fma(svy, sWs[a*128 + i], acc[a]));
    }
    float2* X = d_X + (size_t)img*128*65;
    const float s = 1.f/16384.f;
    #pragma unroll
    for (int a = 0; a < 4; a++){
        float ax, ay; upk(acc[a], ax, ay);
        X[(size_t)(k1b+a)*65 + k2] = make_float2(ax*s, ay*s);
    }
}

// ---------------- zero x_out ----------------
__global__ void kzero_kernel(){
    size_t n = (size_t)BC*64*33;
    for (size_t i = (size_t)blockIdx.x*blockDim.x + threadIdx.x; i < n;
         i += (size_t)gridDim.x*blockDim.x)
        d_xo[i] = make_float2(0.f, 0.f);
}

// ---------------- K1: band crop + inverse row DFT, radix-2 DIT (f32x2) ----------------
__global__ void k1_kernel(int r){
    __shared__ u64 sWp[2][64], sWf[2][64];
    int ty = threadIdx.y, tx = threadIdx.x;
    int tid = ty*blockDim.x + tx, nt = blockDim.x*blockDim.y;
    int m = r/2;
    int p0 = blockIdx.x*2;
    const float2* Wh  = d_W  + offW(m);
    const float2* Whf = d_Wf + offW(m);
    for (int idx = tid; idx < 2*m; idx += nt){
        int a = idx / m, j = idx - a*m;
        int n1 = p0 + a;
        if (n1 < m){
            float2 w = Wh[n1*m + j];  sWp[a][j] = pk2(w.x, w.y);
            float2 f = Whf[n1*m + j]; sWf[a][j] = pk2(f.x, f.y);
        }
    }
    __syncthreads();
    int img = blockIdx.y*blockDim.y + ty;
    int c = m + 1, half = m;
    int k2 = tx;
    if (k2 >= c) return;
    const float2* Xi = d_X  + (size_t)img*128*65;
    float2*       T  = d_T1 + (size_t)img*128*65;
    u64 E0=0,O0=0,E1=0,O1=0;
    for (int j = 0; j < m; j++){
        int je = 2*j, jo = 2*j + 1;
        int srcE = je + ((je >= half) ? (128 - r) : 0);
        int srcO = jo + ((jo >= half) ? (128 - r) : 0);
        float2 ve = Xi[(size_t)srcE*65 + k2];
        float2 vo = Xi[(size_t)srcO*65 + k2];
        u64 sex = sp2(ve.x), sey = sp2(ve.y), sox = sp2(vo.x), soy = sp2(vo.y);
        E0 = f2fma(sex, sWp[0][j], f2fma(sey, sWf[0][j], E0));
        O0 = f2fma(sox, sWp[0][j], f2fma(soy, sWf[0][j], O0));
        E1 = f2fma(sex, sWp[1][j], f2fma(sey, sWf[1][j], E1));
        O1 = f2fma(sox, sWp[1][j], f2fma(soy, sWf[1][j], O1));
    }
    const float2* Wr = d_W + offW(r) + r;   // row 1 of W_r
    #pragma unroll
    for (int a = 0; a < 2; a++){
        int n1 = p0 + a;
        if (n1 >= m) break;
        float Ex,Ey,Ox,Oy;
        upk(a ? E1 : E0, Ex, Ey);
        upk(a ? O1 : O0, Ox, Oy);
        float2 t = Wr[n1];
        float px = t.x*Ox - t.y*Oy, py = t.x*Oy + t.y*Ox;
        T[(size_t)n1*65 + k2]      = make_float2(Ex + px, Ey + py);
        T[(size_t)(n1+m)*65 + k2]  = make_float2(Ex - px, Ey - py);
    }
}

// ---------------- K1 radix-4: r % 4 == 0 && r >= 32 (f32x2) ----------------
__global__ void k1r4_kernel(int r){
    __shared__ u64 sWp[32], sWf[32];
    int ty = threadIdx.y, tx = threadIdx.x;
    int tid = ty*blockDim.x + tx, nt = blockDim.x*blockDim.y;
    int m = r/2, h = r/4;
    int n = blockIdx.x;
    const float2* Wh  = d_W  + offW(h);
    const float2* Whf = d_Wf + offW(h);
    for (int idx = tid; idx < h; idx += nt){
        float2 w = Wh[n*h + idx];  sWp[idx] = pk2(w.x, w.y);
        float2 f = Whf[n*h + idx]; sWf[idx] = pk2(f.x, f.y);
    }
    __syncthreads();
    int img = blockIdx.y*blockDim.y + ty;
    int c = m + 1;
    int k2 = tx;
    if (k2 >= c) return;
    const float2* Xi = d_X  + (size_t)img*128*65;
    float2*       T  = d_T1 + (size_t)img*128*65;
    u64 EE=0,EO=0,OE=0,OO=0;
    int sh = 128 - r;
    for (int j2 = 0; j2 < h; j2++){
        int j0 = 4*j2, j1 = j0+1, jb = j0+2, j3 = j0+3;
        float2 v0 = Xi[(size_t)(j0 + ((j0>=m)?sh:0))*65 + k2];
        float2 v1 = Xi[(size_t)(j1 + ((j1>=m)?sh:0))*65 + k2];
        float2 v2 = Xi[(size_t)(jb + ((jb>=m)?sh:0))*65 + k2];
        float2 v3 = Xi[(size_t)(j3 + ((j3>=m)?sh:0))*65 + k2];
        u64 wp = sWp[j2], wf = sWf[j2];
        EE = f2fma(sp2(v0.x), wp, f2fma(sp2(v0.y), wf, EE));
        OE = f2fma(sp2(v1.x), wp, f2fma(sp2(v1.y), wf, OE));
        EO = f2fma(sp2(v2.x), wp, f2fma(sp2(v2.y), wf, EO));
        OO = f2fma(sp2(v3.x), wp, f2fma(sp2(v3.y), wf, OO));
    }
    float EEx,EEy,EOx,EOy,OEx,OEy,OOx,OOy;
    upk(EE,EEx,EEy); upk(EO,EOx,EOy); upk(OE,OEx,OEy); upk(OO,OOx,OOy);
    const float2* Wm1 = d_W + offW(m) + m;   // row 1 of W_m
    const float2* Wr1 = d_W + offW(r) + r;   // row 1 of W_r
    float2 tm = Wm1[n];
    float2 tr0 = Wr1[n], tr1 = Wr1[n+h];
    float tEOx = tm.x*EOx - tm.y*EOy, tEOy = tm.x*EOy + tm.y*EOx;
    float tOOx = tm.x*OOx - tm.y*OOy, tOOy = tm.x*OOy + tm.y*OOx;
    float E0x = EEx+tEOx, E0y = EEy+tEOy;
    float E1x = EEx-tEOx, E1y = EEy-tEOy;
    float O0x = OEx+tOOx, O0y = OEy+tOOy;
    float O1x = OEx-tOOx, O1y = OEy-tOOy;
    float p0x = tr0.x*O0x - tr0.y*O0y, p0y = tr0.x*O0y + tr0.y*O0x;
    float p1x = tr1.x*O1x - tr1.y*O1y, p1y = tr1.x*O1y + tr1.y*O1x;
    T[(size_t)n*65 + k2]         = make_float2(E0x+p0x, E0y+p0y);
    T[(size_t)(n+m)*65 + k2]     = make_float2(E0x-p0x, E0y-p0y);
    T[(size_t)(n+h)*65 + k2]     = make_float2(E1x+p1x, E1y+p1y);
    T[(size_t)(n+h+m)*65 + k2]   = make_float2(E1x-p1x, E1y-p1y);
}

// ---------------- K2: inverse real DFT over cols, radix-2 over k + gelu (f32x2) ----------------
// Coefficients packed across the two rows (A,B) per lane.
__global__ void k2_kernel(int r){
    __shared__ u64 cEx[8][33], cEy[8][33], cOx[8][33], cOy[8][33];
    int ty = threadIdx.y, tx = threadIdx.x;
    int img = blockIdx.y*blockDim.y + ty;
    int p = blockIdx.x;
    int n1a = 2*p, n1b = n1a + 1;
    int m = r/2, c = m + 1;
    int mE = m/2 + 1;
    int mO = c - mE;
    const float2* T = d_T1 + (size_t)img*128*65;
    for (int k = tx; k < c; k += blockDim.x){
        float wk = (k == 0 || k == m) ? 1.f : 2.f;
        float2 va = T[(size_t)n1a*65 + k];
        float2 vb = T[(size_t)n1b*65 + k];
        u64 px = pk2(wk*va.x, wk*vb.x);
        u64 py = pk2(wk*va.y, wk*vb.y);
        if (k & 1){ cOx[ty][k>>1] = px; cOy[ty][k>>1] = py; }
        else      { cEx[ty][k>>1] = px; cEy[ty][k>>1] = py; }
    }
    __syncthreads();
    int n2 = tx;
    if (n2 >= m) return;
    const float2* Wm = d_W + offW(m);
    u64 e2 = 0, ox2 = 0, oy2 = 0;
    for (int k = 0; k < mO; k++){
        float2 w = Wm[k*m + n2];
        u64 swx = sp2(w.x), swy = sp2(w.y), swyn = sp2(-w.y);
        e2  = f2fma(swx, cEx[ty][k], f2fma(swyn, cEy[ty][k], e2));
        ox2 = f2fma(swx, cOx[ty][k], f2fma(swyn, cOy[ty][k], ox2));
        oy2 = f2fma(swy, cOx[ty][k], f2fma(swx,  cOy[ty][k], oy2));
    }
    if (mE > mO){
        float2 w = Wm[(mE-1)*m + n2];
        e2 = f2fma(sp2(w.x), cEx[ty][mE-1], f2fma(sp2(-w.y), cEy[ty][mE-1], e2));
    }
    float eA,eB,oAx,oBx,oAy,oBy;
    upk(e2,eA,eB); upk(ox2,oAx,oBx); upk(oy2,oAy,oBy);
    float2 t = d_W[offW(r) + r + n2];
    float rA = t.x*oAx - t.y*oAy;
    float rB = t.x*oBx - t.y*oBy;
    float a0 = eA + rA, a2 = eA - rA;
    float b0 = eB + rB, b2 = eB - rB;
    const float K = 0.70710678118654752f;
    a0 = 0.5f*a0*(1.f + erff(a0*K));
    a2 = 0.5f*a2*(1.f + erff(a2*K));
    b0 = 0.5f*b0*(1.f + erff(b0*K));
    b2 = 0.5f*b2*(1.f + erff(b2*K));
    float* u = d_u + (size_t)img*128*128;
    u[(size_t)n1a*128 + n2]     = a0;
    u[(size_t)n1a*128 + n2 + m] = a2;
    u[(size_t)n1b*128 + n2]     = b0;
    u[(size_t)n1b*128 + n2 + m] = b2;
}

// ---------------- K3: forward row DFT at kept freqs, fold (f32x2); store q < nq ----------------
// Accumulate Σ u * w packed, conjugate at the end (u real).
__global__ void k3_kernel(int r, int m, int rp){
    __shared__ u64 sW3[2][64];
    int ty = threadIdx.y, tx = threadIdx.x;
    int tid = ty*blockDim.x + tx, nt = blockDim.x*blockDim.y;
    int nq = m/2 + 1;
    int q0 = blockIdx.x*2;
    const float2* Wh = d_W + offW(m);
    for (int idx = tid; idx < 2*m; idx += nt){
        int a = idx / m, j = idx - a*m;
        int q = q0 + a;
        if (q < nq){ float2 w = Wh[q*m + j]; sW3[a][j] = pk2(w.x, w.y); }
        else sW3[a][j] = 0;
    }
    __syncthreads();
    int img = blockIdx.y*blockDim.y + ty;
    int n2 = tx;
    if (n2 >= r) return;
    const float* u = d_u + (size_t)img*128*128;
    u64 E0=0,O0=0,E1=0,O1=0;
    for (int j = 0; j < m; j++){
        u64 sue = sp2(u[(size_t)(2*j)*128 + n2]);
        u64 suo = sp2(u[(size_t)(2*j+1)*128 + n2]);
        u64 w0 = sW3[0][j], w1 = sW3[1][j];
        E0 = f2fma(sue, w0, E0);
        O0 = f2fma(suo, w0, O0);
        E1 = f2fma(sue, w1, E1);
        O1 = f2fma(suo, w1, O1);
    }
    float2* P = d_P + (size_t)img*64*128;
    const float2* Wr = d_W + offW(r) + r;
    #pragma unroll
    for (int a = 0; a < 2; a++){
        int q = q0 + a;
        if (q >= nq) break;
        float Ex,Eyp,Ox,Oyp;
        upk(a ? E1 : E0, Ex, Eyp);
        upk(a ? O1 : O0, Ox, Oyp);
        float Ey = -Eyp, Oy = -Oyp;   // conj: true DFT of real input
        int kq = (q < rp) ? q : (r - m + q);
        float2 t = Wr[kq];
        float tx1 = t.x, ty1 = -t.y;
        float2 A;
        A.x = Ex + tx1*Ox - ty1*Oy;
        A.y = Ey + tx1*Oy + ty1*Ox;
        P[(size_t)q*128 + n2] = A;
    }
}

// ---------------- K4: col DFT with Hermitian +/- trick; q and m-q per pass ----------------
__global__ void k4_kernel(int r, int c2, float invr2, int m, int nq){
    __shared__ float2 sP[8][2][128];
    int ty = threadIdx.y, tx = threadIdx.x;
    int img = blockIdx.y*blockDim.y + ty;
    int q0 = blockIdx.x*2, q1 = q0 + 1;
    const float2* P = d_P + (size_t)img*64*128;
    for (int i = tx; i < r; i += blockDim.x){
        sP[ty][0][i] = P[(size_t)q0*128 + i];
        sP[ty][1][i] = (q1 < nq) ? P[(size_t)q1*128 + i] : make_float2(0.f,0.f);
    }
    __syncthreads();
    int k2 = tx;
    if (k2 >= c2) return;
    const float2* W = d_W + offW(r);
    float S0=0.f,S1=0.f,S2=0.f,S3=0.f;
    float T0=0.f,T1=0.f,T2=0.f,T3=0.f;
    for (int n2 = 0; n2 < r; n2++){
        float2 w = W[n2*r + k2];
        float2 v0 = sP[ty][0][n2], v1 = sP[ty][1][n2];
        S0 = fmaf(v0.x, w.x, S0); S1 = fmaf(v0.y, w.y, S1);
        S2 = fmaf(v0.x, w.y, S2); S3 = fmaf(v0.y, w.x, S3);
        T0 = fmaf(v1.x, w.x, T0); T1 = fmaf(v1.y, w.y, T1);
        T2 = fmaf(v1.x, w.y, T2); T3 = fmaf(v1.y, w.x, T3);
    }
    float2* U = d_U + (size_t)img*64*33;
    int qcap = m - nq;
    U[(size_t)q0*33 + k2] = make_float2((S0+S1)*invr2, (S3-S2)*invr2);
    if (q0 >= 1 && q0 <= qcap)
        U[(size_t)(m-q0)*33 + k2] = make_float2((S0-S1)*invr2, (-S2-S3)*invr2);
    if (q1 < nq){
        U[(size_t)q1*33 + k2] = make_float2((T0+T1)*invr2, (T3-T2)*invr2);
        if (q1 <= qcap)
            U[(size_t)(m-q1)*33 + k2] = make_float2((T0-T1)*invr2, (-T2-T3)*invr2);
    }
}

// ---------------- K5: inverse row DFT, radix-2 over (n1, n1+m) via kq parity ----------------
__global__ void k5_kernel(int r, int m, int rp, int c2){
    __shared__ int   perm[64];
    __shared__ int   sNe;
    __shared__ float2 sW5[2][64];
    int ty = threadIdx.y, tx = threadIdx.x;
    int tid = ty*blockDim.x + tx, nt = blockDim.x*blockDim.y;
    if (tid == 0){
        int ie = 0;
        for (int q = 0; q < m; q++){
            int kq = (q < rp) ? q : (r - m + q);
            if (!(kq & 1)) perm[ie++] = q;
        }
        sNe = ie;
        for (int q = 0; q < m; q++){
            int kq = (q < rp) ? q : (r - m + q);
            if (kq & 1) perm[ie++] = q;
        }
    }
    __syncthreads();
    int n10 = blockIdx.x*2;
    const float2* W = d_W + offW(r);
    for (int idx = tid; idx < 2*m; idx += nt){
        int a = idx / m, i = idx - a*m;
        int n1 = n10 + a;
        if (n1 < m){
            int q = perm[i];
            int kq = (q < rp) ? q : (r - m + q);
            sW5[a][i] = W[n1*r + kq];
        }
    }
    __syncthreads();
    int img = blockIdx.y*blockDim.y + ty;
    int k2 = tx;
    if (k2 >= c2) return;
    int ne = sNe;
    const float2* U = d_U + (size_t)img*64*33;
    float2 Se0={0.f,0.f},So0={0.f,0.f},Se1={0.f,0.f},So1={0.f,0.f};
    for (int i = 0; i < ne; i++){
        float2 v = U[(size_t)perm[i]*33 + k2];
        float2 w0 = sW5[0][i], w1 = sW5[1][i];
        Se0.x = fmaf(v.x, w0.x, fmaf(-v.y, w0.y, Se0.x));
        Se0.y = fmaf(v.x, w0.y, fmaf( v.y, w0.x, Se0.y));
        Se1.x = fmaf(v.x, w1.x, fmaf(-v.y, w1.y, Se1.x));
        Se1.y = fmaf(v.x, w1.y, fmaf( v.y, w1.x, Se1.y));
    }
    for (int i = ne; i < m; i++){
        float2 v = U[(size_t)perm[i]*33 + k2];
        float2 w0 = sW5[0][i], w1 = sW5[1][i];
        So0.x = fmaf(v.x, w0.x, fmaf(-v.y, w0.y, So0.x));
        So0.y = fmaf(v.x, w0.y, fmaf( v.y, w0.x, So0.y));
        So1.x = fmaf(v.x, w1.x, fmaf(-v.y, w1.y, So1.x));
        So1.y = fmaf(v.x, w1.y, fmaf( v.y, w1.x, So1.y));
    }
    float2* T2 = d_T2 + (size_t)img*128*33;
    int n1a = n10, n1b = n10 + 1;
    T2[(size_t)n1a*33 + k2]     = make_float2(Se0.x+So0.x, Se0.y+So0.y);
    T2[(size_t)(n1a+m)*33 + k2] = make_float2(Se0.x-So0.x, Se0.y-So0.y);
    if (n1b < m){
        T2[(size_t)n1b*33 + k2]     = make_float2(Se1.x+So1.x, Se1.y+So1.y);
        T2[(size_t)(n1b+m)*33 + k2] = make_float2(Se1.x-So1.x, Se1.y-So1.y);
    }
}

// ---------------- K6: inverse real DFT over cols, radix-2 over k + maxpool (f32x2) ----------------
__global__ void k6_kernel(int r, int c2){
    __shared__ u64 cEx[8][17], cEy[8][17], cOx[8][17], cOy[8][17];
    __shared__ float sv[8][128];
    int ty = threadIdx.y, tx = threadIdx.x;
    int img = blockIdx.y*blockDim.y + ty;
    int p = blockIdx.x;
    int n1a = 2*p, n1b = 2*p + 1;
    int m = r/2;
    int nE = (c2 + 1)/2, nO = c2/2;
    const float2* T2 = d_T2 + (size_t)img*128*33;
    for (int k = tx; k < c2; k += blockDim.x){
        float wk = (k == 0) ? 1.f : 2.f;
        float2 a = T2[(size_t)n1a*33 + k];
        float2 b = T2[(size_t)n1b*33 + k];
        u64 px = pk2(wk*a.x, wk*b.x);
        u64 py = pk2(wk*a.y, wk*b.y);
        if (k & 1){ cOx[ty][k>>1] = px; cOy[ty][k>>1] = py; }
        else      { cEx[ty][k>>1] = px; cEy[ty][k>>1] = py; }
    }
    __syncthreads();
    int n2 = tx;
    if (n2 < m){
        const float2* Wm = d_W + offW(m);
        u64 e2 = 0, ox2 = 0, oy2 = 0;
        for (int k = 0; k < nO; k++){
            float2 w = Wm[k*m + n2];
            u64 swx = sp2(w.x), swy = sp2(w.y), swyn = sp2(-w.y);
            e2  = f2fma(swx, cEx[ty][k], f2fma(swyn, cEy[ty][k], e2));
            ox2 = f2fma(swx, cOx[ty][k], f2fma(swyn, cOy[ty][k], ox2));
            oy2 = f2fma(swy, cOx[ty][k], f2fma(swx,  cOy[ty][k], oy2));
        }
        if (nE > nO){
            float2 w = Wm[(nE-1)*m + n2];
            e2 = f2fma(sp2(w.x), cEx[ty][nE-1], f2fma(sp2(-w.y), cEy[ty][nE-1], e2));
        }
        float eA,eB,oAx,oBx,oAy,oBy;
        upk(e2,eA,eB); upk(ox2,oAx,oBx); upk(oy2,oAy,oBy);
        float2 t = d_W[offW(r) + r + n2];
        float rA = t.x*oAx - t.y*oAy;
        float rB = t.x*oBx - t.y*oBy;
        sv[ty][n2]     = fmaxf(eA + rA, eB + rB);
        sv[ty][n2 + m] = fmaxf(eA - rA, eB - rB);
    }
    __syncthreads();
    if (n2 < m){
        float* w = d_w + (size_t)img*64*64;
        w[(size_t)p*64 + n2] = fmaxf(sv[ty][2*n2], sv[ty][2*n2+1]);
    }
}

// ---------------- K8a: forward DFT over cols of pooled image (4 rows/block) ----------------
__global__ void k8a_kernel(int cp, int ncol){
    __shared__ float srow[8][4][64];
    int ty = threadIdx.y, tx = threadIdx.x;
    int img = blockIdx.y*blockDim.y + ty;
    int n1b = blockIdx.x*4;
    const float* wi = d_w + (size_t)img*64*64;
    for (int idx = tx; idx < 4*64; idx += blockDim.x){
        int a = idx >> 6, j = idx & 63;
        int n1 = n1b + a;
        srow[ty][a][j] = (n1 < cp && j < cp) ? wi[(size_t)n1*64 + j] : 0.f;
    }
    __syncthreads();
    int k2 = tx;
    if (k2 >= ncol) return;
    const u64* W = reinterpret_cast<const u64*>(d_W + offW(cp));
    u64 A[4] = {0,0,0,0};
    for (int n2 = 0; n2 < cp; n2++){
        u64 w2 = W[n2*cp + k2];
        #pragma unroll
        for (int a = 0; a < 4; a++)
            A[a] = f2fma(sp2(srow[ty][a][n2]), w2, A[a]);
    }
    float2* G = d_G + (size_t)img*64*33;
    #pragma unroll
    for (int a = 0; a < 4; a++){
        int n1 = n1b + a;
        if (n1 < cp){
            float ax, ay; upk(A[a], ax, ay);
            G[(size_t)n1*33 + k2] = make_float2(ax, -ay);
        }
    }
}

// ---------------- K8b: shell entries of xf = rfft2(w)/cp^2, scatter into x_out ----------------
__global__ void k8b_kernel(int cp){
    __shared__ float2 tw[64];
    int img = blockIdx.x;
    {
        const float2* W = d_W + offW(cp);
        for (int t = threadIdx.x; t < cp; t += blockDim.x) tw[t] = W[cp + t];
    }
    __syncthreads();
    int h = cp/2;
    int codd = cp & 1;
    int nE = (codd ? 2*(h+1) : (h+1)) + cp;
    int e = threadIdx.x;
    if (e >= nE) return;
    int rho, k2, trow;
    if (codd){
        if (e < h+1)            { rho = h;   k2 = e;        trow = h; }
        else if (e < 2*(h+1))   { rho = h+1; k2 = e-(h+1);  trow = 64-h; }
        else { int q = e - 2*(h+1); rho = q; k2 = h; trow = (q <= h) ? q : 64 - (cp - q); }
    } else {
        if (e < h+1)            { rho = h;   k2 = e;        trow = 64-h; }
        else { int q = e - (h+1);   rho = q; k2 = h; trow = (q < h) ? q : 64 - (cp - q); }
    }
    const float2* G = d_G + (size_t)img*64*33;
    float2 A = make_float2(0.f,0.f); int t = 0;
    for (int n1 = 0; n1 < cp; n1++){
        float2 v = G[(size_t)n1*33 + k2];
        float2 w = tw[t];
        A.x = fmaf(v.x, w.x, fmaf( v.y, w.y, A.x));
        A.y = fmaf(v.y, w.x, fmaf(-v.x, w.y, A.y));
        t += rho; if (t >= cp) t -= cp;
    }
    float inv = 1.f/((float)cp*(float)cp);
    d_xo[(size_t)img*64*33 + (size_t)trow*33 + k2] = make_float2(A.x*inv, A.y*inv);
}

// ---------------- K8base: full 8x5 spectrum block for base resolution ----------------
__global__ void k8base_kernel(){
    int img = blockIdx.x;
    int e = threadIdx.x;
    if (e >= 40) return;
    int q = e/5, k2 = e%5;
    const float2* W8 = d_W;
    const float2* G = d_G + (size_t)img*64*33;
    float2 A = make_float2(0.f,0.f);
    for (int n1 = 0; n1 < 8; n1++){
        float2 v = G[(size_t)n1*33 + k2];
        float2 w = W8[q*8 + n1];
        A.x = fmaf(v.x, w.x, fmaf( v.y, w.y, A.x));
        A.y = fmaf(v.y, w.x, fmaf(-v.x, w.y, A.y));
    }
    int trow = (q < 4) ? q : (56 + q);
    d_xo[(size_t)img*64*33 + (size_t)trow*33 + k2] = make_float2(A.x*(1.f/64.f), A.y*(1.f/64.f));
}

// ---------------- K9: analytic fft2(irfft2(x_out)) symmetrization -> output ----------------
__global__ void k9_kernel(float* __restrict__ out){
    int img = blockIdx.y;
    int k1  = blockIdx.x;
    int k2  = threadIdx.x;
    const float2* xo = d_xo + (size_t)img*64*33;
    int k1n = (64 - k1) & 63;
    float2 v;
    if (k2 >= 1 && k2 <= 31){
        v = xo[(size_t)k1*33 + k2];
    } else if (k2 >= 33){
        float2 a = xo[(size_t)k1n*33 + (64 - k2)];
        v = make_float2(a.x, -a.y);
    } else {
        float2 a = xo[(size_t)k1*33 + k2];
        float2 b = xo[(size_t)k1n*33 + k2];
        v = make_float2(0.5f*(a.x + b.x), 0.5f*(a.y - b.y));
    }
    size_t o = (((size_t)img*64 + k1)*64 + k2)*2;
    out[o]   = v.x;
    out[o+1] = v.y;
}

static inline int rup32(int n){ return ((n + 31)/32)*32; }
static inline int imbFor(int tx){
    int i = 256 / tx;
    if (i > 8) i = 8;
    if (i < 1) i = 1;
    while (i & (i-1)) i--;
    return i;
}

extern "C" void kernel_launch(void* const* d_in, const int* in_sizes, int n_in,
                              void* d_out, int out_size){
    const float* x = (const float*)d_in[0];
    float* out = (float*)d_out;
    (void)in_sizes; (void)n_in; (void)out_size;

    kW_kernel<<<121, 256>>>();

    k0a_kernel<<<dim3(32, BC/2), dim3(96, 2)>>>(x);
    k0b_kernel<<<dim3(32, BC/2), dim3(96, 2)>>>();
    kzero_kernel<<<2048, 256>>>();

    for (int r = 16; r <= 128; r += 2){
        int c    = r/2 + 1;
        int m    = r/2;
        int rp   = (m + 1)/2;
        int c2   = m/2 + 1;
        int cp   = r/2;
        int ncol = cp/2 + 1;
        int nq   = m/2 + 1;
        float invr2 = 1.f/((float)r*(float)r);

        int TX1 = rup32(c),    I1 = imbFor(TX1);
        int TX2 = rup32(r),    I2 = imbFor(TX2);
        int TXm = rup32(m),    Im = imbFor(TXm);
        int TX4 = rup32(c2),   I4 = imbFor(TX4);
        int TX8 = rup32(ncol), I8 = imbFor(TX8);

        if ((r % 4) == 0 && r >= 32)
            k1r4_kernel<<<dim3(r/4,     BC/I1), dim3(TX1, I1)>>>(r);
        else
            k1_kernel  <<<dim3((m+1)/2, BC/I1), dim3(TX1, I1)>>>(r);
        k2_kernel <<<dim3(r/2,      BC/Im), dim3(TXm, Im)>>>(r);
        k3_kernel <<<dim3((nq+1)/2, BC/I2), dim3(TX2, I2)>>>(r, m, rp);
        k4_kernel <<<dim3((nq+1)/2, BC/I4), dim3(TX4, I4)>>>(r, c2, invr2, m, nq);
        k5_kernel <<<dim3((m+1)/2,  BC/I4), dim3(TX4, I4)>>>(r, m, rp, c2);
        k6_kernel <<<dim3(r/2,      BC/Im), dim3(TXm, Im)>>>(r, c2);
        k8a_kernel<<<dim3((cp+3)/4, BC/I8), dim3(TX8, I8)>>>(cp, ncol);
        if (r == 16) k8base_kernel<<<BC, 64>>>();
        else         k8b_kernel<<<BC, 128>>>(cp);
    }

    k9_kernel<<<dim3(64, BC), 64>>>(out);
}

// round 16
// speedup vs baseline: 1.1546x; 1.1546x over previous
#include <cuda_runtime.h>
#include <math.h>

#define BC 2048   // 32 batch * 64 channels
typedef unsigned long long u64;

// ---------------- scratch (device globals: allocation-free) ----------------
__device__ float2 d_X   [BC*128*65];
__device__ float2 d_T1  [BC*128*65];
__device__ float  d_u   [BC*128*128];
__device__ float2 d_P   [BC*64*128];
__device__ float2 d_U   [BC*64*33];
__device__ float2 d_T2  [BC*128*33];
__device__ float  d_w   [BC*64*64];
__device__ float2 d_G   [BC*64*33];
__device__ float2 d_xo  [BC*64*33];
// DFT matrices W_n[a*n+b] = e^{+2pi i (a*b mod n)/n} for n = 8..128, and flip (-wy, wx)
__device__ float2 d_W   [707124];
__device__ float2 d_Wf  [707124];

__host__ __device__ __forceinline__ long long offW(int n){
    long long x = n - 1;
    return x*(x+1)*(2*x+1)/6 - 140;   // sum_{m=8}^{n-1} m^2
}

// ---------------- packed f32x2 helpers ----------------
__device__ __forceinline__ u64 pk2(float lo, float hi){ u64 r; asm("mov.b64 %0, {%1,%2};" : "=l"(r) : "f"(lo), "f"(hi)); return r; }
__device__ __forceinline__ u64 sp2(float v){ u64 r; asm("mov.b64 %0, {%1,%1};" : "=l"(r) : "f"(v)); return r; }
__device__ __forceinline__ void upk(u64 p, float& lo, float& hi){ asm("mov.b64 {%0,%1}, %2;" : "=f"(lo), "=f"(hi) : "l"(p)); }
__device__ __forceinline__ u64 f2fma(u64 a, u64 b, u64 c){ u64 d; asm("fma.rn.f32x2 %0, %1, %2, %3;" : "=l"(d) : "l"(a), "l"(b), "l"(c)); return d; }

// ---------------- build all DFT matrices ----------------
__global__ void kW_kernel(){
    int n = blockIdx.x + 8;
    float2* W  = d_W  + offW(n);
    float2* Wf = d_Wf + offW(n);
    int nn = n*n;
    float inv = 1.0f/(float)n;
    for (int idx = threadIdx.x; idx < nn; idx += blockDim.x){
        int a = idx / n, b = idx - a*n;
        int t = (int)(((long long)a*(long long)b) % (long long)n);
        float s, c;
        sincospif(2.0f*(float)t*inv, &s, &c);
        W[idx]  = make_float2(c, s);
        Wf[idx] = make_float2(-s, c);
    }
}

// ---------------- K0a: row-axis forward DFT of input (4 rows/block, f32x2) ----------------
__global__ void k0a_kernel(const float* __restrict__ x){
    __shared__ float s0[2][4][128];
    int ty = threadIdx.y, tx = threadIdx.x;
    int img = blockIdx.y*blockDim.y + ty;
    int i0 = blockIdx.x*4;
    const float* xi = x + (size_t)img*128*128 + (size_t)i0*128;
    for (int idx = tx; idx < 4*128; idx += blockDim.x)
        s0[ty][idx>>7][idx&127] = xi[idx];
    __syncthreads();
    int k2 = tx;
    if (k2 >= 65) return;
    const u64* W = reinterpret_cast<const u64*>(d_W + offW(128));
    u64 P0=0,P1=0,P2=0,P3=0;
    for (int n2 = 0; n2 < 128; n2++){
        u64 w2 = W[n2*128 + k2];
        u64 v0=sp2(s0[ty][0][n2]), v1=sp2(s0[ty][1][n2]), v2=sp2(s0[ty][2][n2]), v3=sp2(s0[ty][3][n2]);
        P0 = f2fma(v0, w2, P0);
        P1 = f2fma(v1, w2, P1);
        P2 = f2fma(v2, w2, P2);
        P3 = f2fma(v3, w2, P3);
    }
    float2* T = d_T1 + (size_t)img*128*65;
    float ax, ay;
    upk(P0, ax, ay); T[(size_t)(i0+0)*65+k2] = make_float2(ax, -ay);
    upk(P1, ax, ay); T[(size_t)(i0+1)*65+k2] = make_float2(ax, -ay);
    upk(P2, ax, ay); T[(size_t)(i0+2)*65+k2] = make_float2(ax, -ay);
    upk(P3, ax, ay); T[(size_t)(i0+3)*65+k2] = make_float2(ax, -ay);
}

// ---------------- K0b: col-axis forward DFT -> X (with 1/128^2, f32x2) ----------------
__global__ void k0b_kernel(){
    __shared__ u64 sWc[4*128];   // conj(w) = (wx, -wy)
    __shared__ u64 sWs[4*128];   // swap(w) = (wy, wx)
    int ty = threadIdx.y, tx = threadIdx.x;
    int tid = ty*blockDim.x + tx, nt = blockDim.x*blockDim.y;
    int k1b = blockIdx.x*4;
    const float2* W = d_W + offW(128);
    for (int idx = tid; idx < 4*128; idx += nt){
        float2 w = W[(k1b + (idx>>7))*128 + (idx&127)];
        sWc[idx] = pk2(w.x, -w.y);
        sWs[idx] = pk2(w.y,  w.x);
    }
    __syncthreads();
    int img = blockIdx.y*blockDim.y + ty;
    int k2 = tx;
    if (k2 >= 65) return;
    const float2* Ai = d_T1 + (size_t)img*128*65;
    u64 acc[4] = {0,0,0,0};
    for (int i = 0; i < 128; i++){
        float2 v = Ai[(size_t)i*65 + k2];
        u64 svx = sp2(v.x), svy = sp2(v.y);
        #pragma unroll
        for (int a = 0; a < 4; a++)
            acc[a] = f2fma(svx, sWc[a*128 + i], f2fma(svy, sWs[a*128 + i], acc[a]));
    }
    float2* X = d_X + (size_t)img*128*65;
    const float s = 1.f/16384.f;
    #pragma unroll
    for (int a = 0; a < 4; a++){
        float ax, ay; upk(acc[a], ax, ay);
        X[(size_t)(k1b+a)*65 + k2] = make_float2(ax*s, ay*s);
    }
}

// ---------------- zero x_out ----------------
__global__ void kzero_kernel(){
    size_t n = (size_t)BC*64*33;
    for (size_t i = (size_t)blockIdx.x*blockDim.x + threadIdx.x; i < n;
         i += (size_t)gridDim.x*blockDim.x)
        d_xo[i] = make_float2(0.f, 0.f);
}

// ---------------- K1: band crop + inverse row DFT, radix-2 DIT (f32x2, 4 p/block) ----------------
__global__ void k1_kernel(int r){
    __shared__ u64 sWp[4][64], sWf[4][64];
    int ty = threadIdx.y, tx = threadIdx.x;
    int tid = ty*blockDim.x + tx, nt = blockDim.x*blockDim.y;
    int m = r/2;
    int p0 = blockIdx.x*4;
    const float2* Wh  = d_W  + offW(m);
    const float2* Whf = d_Wf + offW(m);
    for (int idx = tid; idx < 4*m; idx += nt){
        int a = idx / m, j = idx - a*m;
        int n1 = p0 + a;
        if (n1 < m){
            float2 w = Wh[n1*m + j];  sWp[a][j] = pk2(w.x, w.y);
            float2 f = Whf[n1*m + j]; sWf[a][j] = pk2(f.x, f.y);
        }
    }
    __syncthreads();
    int img = blockIdx.y*blockDim.y + ty;
    int c = m + 1, half = m;
    int k2 = tx;
    if (k2 >= c) return;
    const float2* Xi = d_X  + (size_t)img*128*65;
    float2*       T  = d_T1 + (size_t)img*128*65;
    u64 E[4] = {0,0,0,0}, O[4] = {0,0,0,0};
    #pragma unroll 2
    for (int j = 0; j < m; j++){
        int je = 2*j, jo = 2*j + 1;
        int srcE = je + ((je >= half) ? (128 - r) : 0);
        int srcO = jo + ((jo >= half) ? (128 - r) : 0);
        float2 ve = Xi[(size_t)srcE*65 + k2];
        float2 vo = Xi[(size_t)srcO*65 + k2];
        u64 sex = sp2(ve.x), sey = sp2(ve.y), sox = sp2(vo.x), soy = sp2(vo.y);
        #pragma unroll
        for (int a = 0; a < 4; a++){
            u64 wp = sWp[a][j], wf = sWf[a][j];
            E[a] = f2fma(sex, wp, f2fma(sey, wf, E[a]));
            O[a] = f2fma(sox, wp, f2fma(soy, wf, O[a]));
        }
    }
    const float2* Wr = d_W + offW(r) + r;   // row 1 of W_r
    #pragma unroll
    for (int a = 0; a < 4; a++){
        int n1 = p0 + a;
        if (n1 >= m) break;
        float Ex,Ey,Ox,Oy;
        upk(E[a], Ex, Ey);
        upk(O[a], Ox, Oy);
        float2 t = Wr[n1];
        float px = t.x*Ox - t.y*Oy, py = t.x*Oy + t.y*Ox;
        T[(size_t)n1*65 + k2]      = make_float2(Ex + px, Ey + py);
        T[(size_t)(n1+m)*65 + k2]  = make_float2(Ex - px, Ey - py);
    }
}

// ---------------- K1 radix-4: r % 4 == 0 && r >= 32 (f32x2, 2 n/block) ----------------
__global__ void k1r4_kernel(int r){
    __shared__ u64 sWp[2][32], sWf[2][32];
    int ty = threadIdx.y, tx = threadIdx.x;
    int tid = ty*blockDim.x + tx, nt = blockDim.x*blockDim.y;
    int m = r/2, h = r/4;
    int n0 = blockIdx.x*2;
    const float2* Wh  = d_W  + offW(h);
    const float2* Whf = d_Wf + offW(h);
    for (int idx = tid; idx < 2*h; idx += nt){
        int a = idx / h, j = idx - a*h;
        int n = n0 + a;
        if (n < h){
            float2 w = Wh[n*h + j];  sWp[a][j] = pk2(w.x, w.y);
            float2 f = Whf[n*h + j]; sWf[a][j] = pk2(f.x, f.y);
        }
    }
    __syncthreads();
    int img = blockIdx.y*blockDim.y + ty;
    int c = m + 1;
    int k2 = tx;
    if (k2 >= c) return;
    const float2* Xi = d_X  + (size_t)img*128*65;
    float2*       T  = d_T1 + (size_t)img*128*65;
    u64 EE[2]={0,0},EO[2]={0,0},OE[2]={0,0},OO[2]={0,0};
    int sh = 128 - r;
    #pragma unroll 2
    for (int j2 = 0; j2 < h; j2++){
        int j0 = 4*j2, j1 = j0+1, jb = j0+2, j3 = j0+3;
        float2 v0 = Xi[(size_t)(j0 + ((j0>=m)?sh:0))*65 + k2];
        float2 v1 = Xi[(size_t)(j1 + ((j1>=m)?sh:0))*65 + k2];
        float2 v2 = Xi[(size_t)(jb + ((jb>=m)?sh:0))*65 + k2];
        float2 v3 = Xi[(size_t)(j3 + ((j3>=m)?sh:0))*65 + k2];
        u64 s0x = sp2(v0.x), s0y = sp2(v0.y), s1x = sp2(v1.x), s1y = sp2(v1.y);
        u64 s2x = sp2(v2.x), s2y = sp2(v2.y), s3x = sp2(v3.x), s3y = sp2(v3.y);
        #pragma unroll
        for (int a = 0; a < 2; a++){
            u64 wp = sWp[a][j2], wf = sWf[a][j2];
            EE[a] = f2fma(s0x, wp, f2fma(s0y, wf, EE[a]));
            OE[a] = f2fma(s1x, wp, f2fma(s1y, wf, OE[a]));
            EO[a] = f2fma(s2x, wp, f2fma(s2y, wf, EO[a]));
            OO[a] = f2fma(s3x, wp, f2fma(s3y, wf, OO[a]));
        }
    }
    const float2* Wm1 = d_W + offW(m) + m;   // row 1 of W_m
    const float2* Wr1 = d_W + offW(r) + r;   // row 1 of W_r
    #pragma unroll
    for (int a = 0; a < 2; a++){
        int n = n0 + a;
        if (n >= h) break;
        float EEx,EEy,EOx,EOy,OEx,OEy,OOx,OOy;
        upk(EE[a],EEx,EEy); upk(EO[a],EOx,EOy); upk(OE[a],OEx,OEy); upk(OO[a],OOx,OOy);
        float2 tm = Wm1[n];
        float2 tr0 = Wr1[n], tr1 = Wr1[n+h];
        float tEOx = tm.x*EOx - tm.y*EOy, tEOy = tm.x*EOy + tm.y*EOx;
        float tOOx = tm.x*OOx - tm.y*OOy, tOOy = tm.x*OOy + tm.y*OOx;
        float E0x = EEx+tEOx, E0y = EEy+tEOy;
        float E1x = EEx-tEOx, E1y = EEy-tEOy;
        float O0x = OEx+tOOx, O0y = OEy+tOOy;
        float O1x = OEx-tOOx, O1y = OEy-tOOy;
        float p0x = tr0.x*O0x - tr0.y*O0y, p0y = tr0.x*O0y + tr0.y*O0x;
        float p1x = tr1.x*O1x - tr1.y*O1y, p1y = tr1.x*O1y + tr1.y*O1x;
        T[(size_t)n*65 + k2]         = make_float2(E0x+p0x, E0y+p0y);
        T[(size_t)(n+m)*65 + k2]     = make_float2(E0x-p0x, E0y-p0y);
        T[(size_t)(n+h)*65 + k2]     = make_float2(E1x+p1x, E1y+p1y);
        T[(size_t)(n+h+m)*65 + k2]   = make_float2(E1x-p1x, E1y-p1y);
    }
}

// ---------------- K2: inverse real DFT over cols, radix-2 over k + gelu (f32x2) ----------------
__global__ void k2_kernel(int r){
    __shared__ u64 cEx[8][33], cEy[8][33], cOx[8][33], cOy[8][33];
    int ty = threadIdx.y, tx = threadIdx.x;
    int img = blockIdx.y*blockDim.y + ty;
    int p = blockIdx.x;
    int n1a = 2*p, n1b = n1a + 1;
    int m = r/2, c = m + 1;
    int mE = m/2 + 1;
    int mO = c - mE;
    const float2* T = d_T1 + (size_t)img*128*65;
    for (int k = tx; k < c; k += blockDim.x){
        float wk = (k == 0 || k == m) ? 1.f : 2.f;
        float2 va = T[(size_t)n1a*65 + k];
        float2 vb = T[(size_t)n1b*65 + k];
        u64 px = pk2(wk*va.x, wk*vb.x);
        u64 py = pk2(wk*va.y, wk*vb.y);
        if (k & 1){ cOx[ty][k>>1] = px; cOy[ty][k>>1] = py; }
        else      { cEx[ty][k>>1] = px; cEy[ty][k>>1] = py; }
    }
    __syncthreads();
    int n2 = tx;
    if (n2 >= m) return;
    const float2* Wm = d_W + offW(m);
    u64 e2 = 0, ox2 = 0, oy2 = 0;
    for (int k = 0; k < mO; k++){
        float2 w = Wm[k*m + n2];
        u64 swx = sp2(w.x), swy = sp2(w.y), swyn = sp2(-w.y);
        e2  = f2fma(swx, cEx[ty][k], f2fma(swyn, cEy[ty][k], e2));
        ox2 = f2fma(swx, cOx[ty][k], f2fma(swyn, cOy[ty][k], ox2));
        oy2 = f2fma(swy, cOx[ty][k], f2fma(swx,  cOy[ty][k], oy2));
    }
    if (mE > mO){
        float2 w = Wm[(mE-1)*m + n2];
        e2 = f2fma(sp2(w.x), cEx[ty][mE-1], f2fma(sp2(-w.y), cEy[ty][mE-1], e2));
    }
    float eA,eB,oAx,oBx,oAy,oBy;
    upk(e2,eA,eB); upk(ox2,oAx,oBx); upk(oy2,oAy,oBy);
    float2 t = d_W[offW(r) + r + n2];
    float rA = t.x*oAx - t.y*oAy;
    float rB = t.x*oBx - t.y*oBy;
    float a0 = eA + rA, a2 = eA - rA;
    float b0 = eB + rB, b2 = eB - rB;
    const float K = 0.70710678118654752f;
    a0 = 0.5f*a0*(1.f + erff(a0*K));
    a2 = 0.5f*a2*(1.f + erff(a2*K));
    b0 = 0.5f*b0*(1.f + erff(b0*K));
    b2 = 0.5f*b2*(1.f + erff(b2*K));
    float* u = d_u + (size_t)img*128*128;
    u[(size_t)n1a*128 + n2]     = a0;
    u[(size_t)n1a*128 + n2 + m] = a2;
    u[(size_t)n1b*128 + n2]     = b0;
    u[(size_t)n1b*128 + n2 + m] = b2;
}

// ---------------- K3: forward row DFT at kept freqs, fold (f32x2, 4 q/block) ----------------
__global__ void k3_kernel(int r, int m, int rp){
    __shared__ u64 sW3[4][64];
    int ty = threadIdx.y, tx = threadIdx.x;
    int tid = ty*blockDim.x + tx, nt = blockDim.x*blockDim.y;
    int nq = m/2 + 1;
    int q0 = blockIdx.x*4;
    const float2* Wh = d_W + offW(m);
    for (int idx = tid; idx < 4*m; idx += nt){
        int a = idx / m, j = idx - a*m;
        int q = q0 + a;
        if (q < nq){ float2 w = Wh[q*m + j]; sW3[a][j] = pk2(w.x, w.y); }
        else sW3[a][j] = 0;
    }
    __syncthreads();
    int img = blockIdx.y*blockDim.y + ty;
    int n2 = tx;
    if (n2 >= r) return;
    const float* u = d_u + (size_t)img*128*128;
    u64 E[4] = {0,0,0,0}, O[4] = {0,0,0,0};
    #pragma unroll 2
    for (int j = 0; j < m; j++){
        u64 sue = sp2(u[(size_t)(2*j)*128 + n2]);
        u64 suo = sp2(u[(size_t)(2*j+1)*128 + n2]);
        #pragma unroll
        for (int a = 0; a < 4; a++){
            u64 w = sW3[a][j];
            E[a] = f2fma(sue, w, E[a]);
            O[a] = f2fma(suo, w, O[a]);
        }
    }
    float2* P = d_P + (size_t)img*64*128;
    const float2* Wr = d_W + offW(r) + r;
    #pragma unroll
    for (int a = 0; a < 4; a++){
        int q = q0 + a;
        if (q >= nq) break;
        float Ex,Eyp,Ox,Oyp;
        upk(E[a], Ex, Eyp);
        upk(O[a], Ox, Oyp);
        float Ey = -Eyp, Oy = -Oyp;   // conj: true DFT of real input
        int kq = (q < rp) ? q : (r - m + q);
        float2 t = Wr[kq];
        float tx1 = t.x, ty1 = -t.y;
        float2 A;
        A.x = Ex + tx1*Ox - ty1*Oy;
        A.y = Ey + tx1*Oy + ty1*Ox;
        P[(size_t)q*128 + n2] = A;
    }
}

// ---------------- K4: col DFT with Hermitian +/- trick; q and m-q per pass ----------------
__global__ void k4_kernel(int r, int c2, float invr2, int m, int nq){
    __shared__ float2 sP[8][2][128];
    int ty = threadIdx.y, tx = threadIdx.x;
    int img = blockIdx.y*blockDim.y + ty;
    int q0 = blockIdx.x*2, q1 = q0 + 1;
    const float2* P = d_P + (size_t)img*64*128;
    for (int i = tx; i < r; i += blockDim.x){
        sP[ty][0][i] = P[(size_t)q0*128 + i];
        sP[ty][1][i] = (q1 < nq) ? P[(size_t)q1*128 + i] : make_float2(0.f,0.f);
    }
    __syncthreads();
    int k2 = tx;
    if (k2 >= c2) return;
    const float2* W = d_W + offW(r);
    float S0=0.f,S1=0.f,S2=0.f,S3=0.f;
    float T0=0.f,T1=0.f,T2=0.f,T3=0.f;
    for (int n2 = 0; n2 < r; n2++){
        float2 w = W[n2*r + k2];
        float2 v0 = sP[ty][0][n2], v1 = sP[ty][1][n2];
        S0 = fmaf(v0.x, w.x, S0); S1 = fmaf(v0.y, w.y, S1);
        S2 = fmaf(v0.x, w.y, S2); S3 = fmaf(v0.y, w.x, S3);
        T0 = fmaf(v1.x, w.x, T0); T1 = fmaf(v1.y, w.y, T1);
        T2 = fmaf(v1.x, w.y, T2); T3 = fmaf(v1.y, w.x, T3);
    }
    float2* U = d_U + (size_t)img*64*33;
    int qcap = m - nq;
    U[(size_t)q0*33 + k2] = make_float2((S0+S1)*invr2, (S3-S2)*invr2);
    if (q0 >= 1 && q0 <= qcap)
        U[(size_t)(m-q0)*33 + k2] = make_float2((S0-S1)*invr2, (-S2-S3)*invr2);
    if (q1 < nq){
        U[(size_t)q1*33 + k2] = make_float2((T0+T1)*invr2, (T3-T2)*invr2);
        if (q1 <= qcap)
            U[(size_t)(m-q1)*33 + k2] = make_float2((T0-T1)*invr2, (-T2-T3)*invr2);
    }
}

// ---------------- K5: inverse row DFT, radix-2 over (n1, n1+m), 4 n1/block ----------------
__global__ void k5_kernel(int r, int m, int rp, int c2){
    __shared__ int   perm[64];
    __shared__ int   sNe;
    __shared__ float2 sW5[4][64];
    int ty = threadIdx.y, tx = threadIdx.x;
    int tid = ty*blockDim.x + tx, nt = blockDim.x*blockDim.y;
    if (tid == 0){
        int ie = 0;
        for (int q = 0; q < m; q++){
            int kq = (q < rp) ? q : (r - m + q);
            if (!(kq & 1)) perm[ie++] = q;
        }
        sNe = ie;
        for (int q = 0; q < m; q++){
            int kq = (q < rp) ? q : (r - m + q);
            if (kq & 1) perm[ie++] = q;
        }
    }
    __syncthreads();
    int n10 = blockIdx.x*4;
    const float2* W = d_W + offW(r);
    for (int idx = tid; idx < 4*m; idx += nt){
        int a = idx / m, i = idx - a*m;
        int n1 = n10 + a;
        if (n1 < m){
            int q = perm[i];
            int kq = (q < rp) ? q : (r - m + q);
            sW5[a][i] = W[n1*r + kq];
        }
    }
    __syncthreads();
    int img = blockIdx.y*blockDim.y + ty;
    int k2 = tx;
    if (k2 >= c2) return;
    int ne = sNe;
    const float2* U = d_U + (size_t)img*64*33;
    float2 Se[4] = {{0.f,0.f},{0.f,0.f},{0.f,0.f},{0.f,0.f}};
    float2 So[4] = {{0.f,0.f},{0.f,0.f},{0.f,0.f},{0.f,0.f}};
    for (int i = 0; i < ne; i++){
        float2 v = U[(size_t)perm[i]*33 + k2];
        #pragma unroll
        for (int a = 0; a < 4; a++){
            float2 w = sW5[a][i];
            Se[a].x = fmaf(v.x, w.x, fmaf(-v.y, w.y, Se[a].x));
            Se[a].y = fmaf(v.x, w.y, fmaf( v.y, w.x, Se[a].y));
        }
    }
    for (int i = ne; i < m; i++){
        float2 v = U[(size_t)perm[i]*33 + k2];
        #pragma unroll
        for (int a = 0; a < 4; a++){
            float2 w = sW5[a][i];
            So[a].x = fmaf(v.x, w.x, fmaf(-v.y, w.y, So[a].x));
            So[a].y = fmaf(v.x, w.y, fmaf( v.y, w.x, So[a].y));
        }
    }
    float2* T2 = d_T2 + (size_t)img*128*33;
    #pragma unroll
    for (int a = 0; a < 4; a++){
        int n1 = n10 + a;
        if (n1 >= m) break;
        T2[(size_t)n1*33 + k2]     = make_float2(Se[a].x+So[a].x, Se[a].y+So[a].y);
        T2[(size_t)(n1+m)*33 + k2] = make_float2(Se[a].x-So[a].x, Se[a].y-So[a].y);
    }
}

// ---------------- K6: inverse real DFT over cols, radix-2 over k + maxpool (f32x2) ----------------
__global__ void k6_kernel(int r, int c2){
    __shared__ u64 cEx[8][17], cEy[8][17], cOx[8][17], cOy[8][17];
    __shared__ float sv[8][128];
    int ty = threadIdx.y, tx = threadIdx.x;
    int img = blockIdx.y*blockDim.y + ty;
    int p = blockIdx.x;
    int n1a = 2*p, n1b = 2*p + 1;
    int m = r/2;
    int nE = (c2 + 1)/2, nO = c2/2;
    const float2* T2 = d_T2 + (size_t)img*128*33;
    for (int k = tx; k < c2; k += blockDim.x){
        float wk = (k == 0) ? 1.f : 2.f;
        float2 a = T2[(size_t)n1a*33 + k];
        float2 b = T2[(size_t)n1b*33 + k];
        u64 px = pk2(wk*a.x, wk*b.x);
        u64 py = pk2(wk*a.y, wk*b.y);
        if (k & 1){ cOx[ty][k>>1] = px; cOy[ty][k>>1] = py; }
        else      { cEx[ty][k>>1] = px; cEy[ty][k>>1] = py; }
    }
    __syncthreads();
    int n2 = tx;
    if (n2 < m){
        const float2* Wm = d_W + offW(m);
        u64 e2 = 0, ox2 = 0, oy2 = 0;
        for (int k = 0; k < nO; k++){
            float2 w = Wm[k*m + n2];
            u64 swx = sp2(w.x), swy = sp2(w.y), swyn = sp2(-w.y);
            e2  = f2fma(swx, cEx[ty][k], f2fma(swyn, cEy[ty][k], e2));
            ox2 = f2fma(swx, cOx[ty][k], f2fma(swyn, cOy[ty][k], ox2));
            oy2 = f2fma(swy, cOx[ty][k], f2fma(swx,  cOy[ty][k], oy2));
        }
        if (nE > nO){
            float2 w = Wm[(nE-1)*m + n2];
            e2 = f2fma(sp2(w.x), cEx[ty][nE-1], f2fma(sp2(-w.y), cEy[ty][nE-1], e2));
        }
        float eA,eB,oAx,oBx,oAy,oBy;
        upk(e2,eA,eB); upk(ox2,oAx,oBx); upk(oy2,oAy,oBy);
        float2 t = d_W[offW(r) + r + n2];
        float rA = t.x*oAx - t.y*oAy;
        float rB = t.x*oBx - t.y*oBy;
        sv[ty][n2]     = fmaxf(eA + rA, eB + rB);
        sv[ty][n2 + m] = fmaxf(eA - rA, eB - rB);
    }
    __syncthreads();
    if (n2 < m){
        float* w = d_w + (size_t)img*64*64;
        w[(size_t)p*64 + n2] = fmaxf(sv[ty][2*n2], sv[ty][2*n2+1]);
    }
}

// ---------------- K8a: forward DFT over cols of pooled image (4 rows/block) ----------------
__global__ void k8a_kernel(int cp, int ncol){
    __shared__ float srow[8][4][64];
    int ty = threadIdx.y, tx = threadIdx.x;
    int img = blockIdx.y*blockDim.y + ty;
    int n1b = blockIdx.x*4;
    const float* wi = d_w + (size_t)img*64*64;
    for (int idx = tx; idx < 4*64; idx += blockDim.x){
        int a = idx >> 6, j = idx & 63;
        int n1 = n1b + a;
        srow[ty][a][j] = (n1 < cp && j < cp) ? wi[(size_t)n1*64 + j] : 0.f;
    }
    __syncthreads();
    int k2 = tx;
    if (k2 >= ncol) return;
    const u64* W = reinterpret_cast<const u64*>(d_W + offW(cp));
    u64 A[4] = {0,0,0,0};
    for (int n2 = 0; n2 < cp; n2++){
        u64 w2 = W[n2*cp + k2];
        #pragma unroll
        for (int a = 0; a < 4; a++)
            A[a] = f2fma(sp2(srow[ty][a][n2]), w2, A[a]);
    }
    float2* G = d_G + (size_t)img*64*33;
    #pragma unroll
    for (int a = 0; a < 4; a++){
        int n1 = n1b + a;
        if (n1 < cp){
            float ax, ay; upk(A[a], ax, ay);
            G[(size_t)n1*33 + k2] = make_float2(ax, -ay);
        }
    }
}

// ---------------- K8b: shell entries of xf = rfft2(w)/cp^2, scatter into x_out ----------------
__global__ void k8b_kernel(int cp){
    __shared__ float2 tw[64];
    int img = blockIdx.x;
    {
        const float2* W = d_W + offW(cp);
        for (int t = threadIdx.x; t < cp; t += blockDim.x) tw[t] = W[cp + t];
    }
    __syncthreads();
    int h = cp/2;
    int codd = cp & 1;
    int nE = (codd ? 2*(h+1) : (h+1)) + cp;
    int e = threadIdx.x;
    if (e >= nE) return;
    int rho, k2, trow;
    if (codd){
        if (e < h+1)            { rho = h;   k2 = e;        trow = h; }
        else if (e < 2*(h+1))   { rho = h+1; k2 = e-(h+1);  trow = 64-h; }
        else { int q = e - 2*(h+1); rho = q; k2 = h; trow = (q <= h) ? q : 64 - (cp - q); }
    } else {
        if (e < h+1)            { rho = h;   k2 = e;        trow = 64-h; }
        else { int q = e - (h+1);   rho = q; k2 = h; trow = (q < h) ? q : 64 - (cp - q); }
    }
    const float2* G = d_G + (size_t)img*64*33;
    float2 A = make_float2(0.f,0.f); int t = 0;
    for (int n1 = 0; n1 < cp; n1++){
        float2 v = G[(size_t)n1*33 + k2];
        float2 w = tw[t];
        A.x = fmaf(v.x, w.x, fmaf( v.y, w.y, A.x));
        A.y = fmaf(v.y, w.x, fmaf(-v.x, w.y, A.y));
        t += rho; if (t >= cp) t -= cp;
    }
    float inv = 1.f/((float)cp*(float)cp);
    d_xo[(size_t)img*64*33 + (size_t)trow*33 + k2] = make_float2(A.x*inv, A.y*inv);
}

// ---------------- K8base: full 8x5 spectrum block for base resolution ----------------
__global__ void k8base_kernel(){
    int img = blockIdx.x;
    int e = threadIdx.x;
    if (e >= 40) return;
    int q = e/5, k2 = e%5;
    const float2* W8 = d_W;
    const float2* G = d_G + (size_t)img*64*33;
    float2 A = make_float2(0.f,0.f);
    for (int n1 = 0; n1 < 8; n1++){
        float2 v = G[(size_t)n1*33 + k2];
        float2 w = W8[q*8 + n1];
        A.x = fmaf(v.x, w.x, fmaf( v.y, w.y, A.x));
        A.y = fmaf(v.y, w.x, fmaf(-v.x, w.y, A.y));
    }
    int trow = (q < 4) ? q : (56 + q);
    d_xo[(size_t)img*64*33 + (size_t)trow*33 + k2] = make_float2(A.x*(1.f/64.f), A.y*(1.f/64.f));
}

// ---------------- K9: analytic fft2(irfft2(x_out)) symmetrization -> output ----------------
__global__ void k9_kernel(float* __restrict__ out){
    int img = blockIdx.y;
    int k1  = blockIdx.x;
    int k2  = threadIdx.x;
    const float2* xo = d_xo + (size_t)img*64*33;
    int k1n = (64 - k1) & 63;
    float2 v;
    if (k2 >= 1 && k2 <= 31){
        v = xo[(size_t)k1*33 + k2];
    } else if (k2 >= 33){
        float2 a = xo[(size_t)k1n*33 + (64 - k2)];
        v = make_float2(a.x, -a.y);
    } else {
        float2 a = xo[(size_t)k1*33 + k2];
        float2 b = xo[(size_t)k1n*33 + k2];
        v = make_float2(0.5f*(a.x + b.x), 0.5f*(a.y - b.y));
    }
    size_t o = (((size_t)img*64 + k1)*64 + k2)*2;
    out[o]   = v.x;
    out[o+1] = v.y;
}

static inline int rup32(int n){ return ((n + 31)/32)*32; }
static inline int imbFor(int tx){
    int i = 256 / tx;
    if (i > 8) i = 8;
    if (i < 1) i = 1;
    while (i & (i-1)) i--;
    return i;
}

extern "C" void kernel_launch(void* const* d_in, const int* in_sizes, int n_in,
                              void* d_out, int out_size){
    const float* x = (const float*)d_in[0];
    float* out = (float*)d_out;
    (void)in_sizes; (void)n_in; (void)out_size;

    kW_kernel<<<121, 256>>>();

    k0a_kernel<<<dim3(32, BC/2), dim3(96, 2)>>>(x);
    k0b_kernel<<<dim3(32, BC/2), dim3(96, 2)>>>();
    kzero_kernel<<<2048, 256>>>();

    for (int r = 16; r <= 128; r += 2){
        int c    = r/2 + 1;
        int m    = r/2;
        int rp   = (m + 1)/2;
        int c2   = m/2 + 1;
        int cp   = r/2;
        int ncol = cp/2 + 1;
        int nq   = m/2 + 1;
        float invr2 = 1.f/((float)r*(float)r);

        int TX1 = rup32(c),    I1 = imbFor(TX1);
        int TX2 = rup32(r),    I2 = imbFor(TX2);
        int TXm = rup32(m),    Im = imbFor(TXm);
        int TX4 = rup32(c2),   I4 = imbFor(TX4);
        int TX8 = rup32(ncol), I8 = imbFor(TX8);

        if ((r % 4) == 0 && r >= 32){
            int h = r/4;
            k1r4_kernel<<<dim3((h+1)/2,  BC/I1), dim3(TX1, I1)>>>(r);
        } else {
            k1_kernel  <<<dim3((m+3)/4,  BC/I1), dim3(TX1, I1)>>>(r);
        }
        k2_kernel <<<dim3(r/2,      BC/Im), dim3(TXm, Im)>>>(r);
        k3_kernel <<<dim3((nq+3)/4, BC/I2), dim3(TX2, I2)>>>(r, m, rp);
        k4_kernel <<<dim3((nq+1)/2, BC/I4), dim3(TX4, I4)>>>(r, c2, invr2, m, nq);
        k5_kernel <<<dim3((m+3)/4,  BC/I4), dim3(TX4, I4)>>>(r, m, rp, c2);
        k6_kernel <<<dim3(r/2,      BC/Im), dim3(TXm, Im)>>>(r, c2);
        k8a_kernel<<<dim3((cp+3)/4, BC/I8), dim3(TX8, I8)>>>(cp, ncol);
        if (r == 16) k8base_kernel<<<BC, 64>>>();
        else         k8b_kernel<<<BC, 128>>>(cp);
    }

    k9_kernel<<<dim3(64, BC), 64>>>(out);
}